// round 12
// baseline (speedup 1.0000x reference)
#include <cuda_runtime.h>
#include <cuda_bf16.h>
#include <stdint.h>
#include <math.h>

// ---------------- problem constants ----------------
#define T_TOK 4096
#define HID   2048
#define NHEAD 16
#define NKVH  8
#define HDIM  128
#define QS    (NHEAD*HDIM)        // 2048
#define KVS   (NKVH*HDIM)         // 1024
#define QKV_N (QS + 2*KVS)        // 4096
#define RSCALE 0.08838834764831845f   // 128^-0.5

// ---------------- scratch (no allocations allowed) ----------------
__device__ float g_qkv[(size_t)T_TOK * QKV_N];   // 64 MB
__device__ float g_att[(size_t)T_TOK * QS];      // 32 MB
__device__ float g_rope[(size_t)T_TOK * HDIM];   // [t][0:64]=cos, [64:128]=sin

// ---------------- helpers ----------------
__device__ __forceinline__ uint32_t f2tf32(float f) {
    uint32_t u;
    asm("cvt.rna.tf32.f32 %0, %1;" : "=r"(u) : "f"(f));
    return u;
}

__device__ __forceinline__ void mma_tf32(float c[4],
    uint32_t a0, uint32_t a1, uint32_t a2, uint32_t a3,
    uint32_t b0, uint32_t b1)
{
    asm volatile(
        "mma.sync.aligned.m16n8k8.row.col.f32.tf32.tf32.f32 "
        "{%0,%1,%2,%3},{%4,%5,%6,%7},{%8,%9},{%0,%1,%2,%3};\n"
        : "+f"(c[0]), "+f"(c[1]), "+f"(c[2]), "+f"(c[3])
        : "r"(a0), "r"(a1), "r"(a2), "r"(a3), "r"(b0), "r"(b1));
}

// ---------------- RoPE cos/sin table ----------------
__global__ void build_rope_kernel(float* __restrict__ tab,
                                  const int* __restrict__ positions)
{
    int i = blockIdx.x * blockDim.x + threadIdx.x;
    if (i >= T_TOK * 64) return;
    int t = i >> 6, j = i & 63;
    float inv = 1.0f / powf(1.0e6f, (float)(2 * j) / 128.0f);
    float ang = (float)positions[t] * inv;
    tab[(size_t)t * 128 + j]      = (float)cos((double)ang);
    tab[(size_t)t * 128 + 64 + j] = (float)sin((double)ang);
}

// ---------------- fused per-head RMSNorm + RoPE (in place on q,k) ----------------
__global__ void norm_rope_kernel(float* __restrict__ qkv,
                                 const float* __restrict__ qw,
                                 const float* __restrict__ kw,
                                 const float* __restrict__ tab)
{
    int t  = blockIdx.x;
    int hh = blockIdx.y;
    bool isq = hh < NHEAD;
    float* x = qkv + (size_t)t * QKV_N + (isq ? hh * HDIM : QS + (hh - NHEAD) * HDIM);
    const float* w = isq ? qw : kw;

    __shared__ float buf[HDIM];
    __shared__ float red[4];
    int d = threadIdx.x;
    float v = x[d];
    float ss = v * v;
    #pragma unroll
    for (int o = 16; o; o >>= 1) ss += __shfl_xor_sync(0xffffffffu, ss, o);
    if ((d & 31) == 0) red[d >> 5] = ss;
    __syncthreads();
    float tot = red[0] + red[1] + red[2] + red[3];
    float r = rsqrtf(tot * (1.0f / HDIM) + 1e-6f);
    buf[d] = v * r * w[d];
    __syncthreads();
    if (d < 64) {
        float x1 = buf[d], x2 = buf[d + 64];
        float c = tab[(size_t)t * 128 + d];
        float s = tab[(size_t)t * 128 + 64 + d];
        x[d]      = x1 * c - x2 * s;
        x[d + 64] = x2 * c + x1 * s;
    }
}

// ---------------- tf32 tensor-core GEMM: C[M,N] = A[M,K] * B[K,N] ----------------
// R5 version (best known): block 128x128x32, 256 threads, warp tile 32x64,
// register-prefetch pipeline, scalar fragment loads.
__global__ __launch_bounds__(256) void gemm_tf32_kernel(
    const float* __restrict__ A, const float* __restrict__ B,
    float* __restrict__ C, int M, int N, int K)
{
    __shared__ uint32_t As[128 * 36];   // pitch 36: conflict-free A frags
    __shared__ uint32_t Bs[32 * 136];   // pitch 136: conflict-free B frags

    const int tid  = threadIdx.x;
    const int lane = tid & 31, warp = tid >> 5;
    const int g  = lane >> 2, tg = lane & 3;
    const int wm = (warp & 3) << 5;
    const int wn = (warp >> 2) << 6;
    const int bm = blockIdx.y << 7, bn = blockIdx.x << 7;

    int ar[4], ac[4], br[4], bc[4];
    #pragma unroll
    for (int it = 0; it < 4; it++) {
        int i = tid + it * 256;
        ar[it] = i >> 3;  ac[it] = (i & 7) << 2;
        br[it] = i >> 5;  bc[it] = (i & 31) << 2;
    }

    float acc[2][8][4];
    #pragma unroll
    for (int mi = 0; mi < 2; mi++)
        #pragma unroll
        for (int ni = 0; ni < 8; ni++)
            #pragma unroll
            for (int c = 0; c < 4; c++) acc[mi][ni][c] = 0.f;

    float4 ra[4], rb[4];
    #pragma unroll
    for (int it = 0; it < 4; it++) {
        ra[it] = *(const float4*)(A + (size_t)(bm + ar[it]) * K + ac[it]);
        rb[it] = *(const float4*)(B + (size_t)br[it] * N + bn + bc[it]);
    }

    for (int k0 = 0; k0 < K; k0 += 32) {
        #pragma unroll
        for (int it = 0; it < 4; it++) {
            *(uint4*)(As + ar[it] * 36 + ac[it]) = make_uint4(
                f2tf32(ra[it].x), f2tf32(ra[it].y), f2tf32(ra[it].z), f2tf32(ra[it].w));
            *(uint4*)(Bs + br[it] * 136 + bc[it]) = make_uint4(
                f2tf32(rb[it].x), f2tf32(rb[it].y), f2tf32(rb[it].z), f2tf32(rb[it].w));
        }
        __syncthreads();

        if (k0 + 32 < K) {
            #pragma unroll
            for (int it = 0; it < 4; it++) {
                ra[it] = *(const float4*)(A + (size_t)(bm + ar[it]) * K + k0 + 32 + ac[it]);
                rb[it] = *(const float4*)(B + (size_t)(k0 + 32 + br[it]) * N + bn + bc[it]);
            }
        }

        #pragma unroll
        for (int kk = 0; kk < 4; kk++) {
            uint32_t a[2][4];
            #pragma unroll
            for (int mi = 0; mi < 2; mi++) {
                const uint32_t* Ap = As + (wm + mi * 16) * 36 + kk * 8;
                a[mi][0] = Ap[g * 36 + tg];
                a[mi][1] = Ap[(g + 8) * 36 + tg];
                a[mi][2] = Ap[g * 36 + tg + 4];
                a[mi][3] = Ap[(g + 8) * 36 + tg + 4];
            }
            #pragma unroll
            for (int ni = 0; ni < 8; ni++) {
                uint32_t b0 = Bs[(kk * 8 + tg) * 136 + wn + ni * 8 + g];
                uint32_t b1 = Bs[(kk * 8 + tg + 4) * 136 + wn + ni * 8 + g];
                #pragma unroll
                for (int mi = 0; mi < 2; mi++)
                    mma_tf32(acc[mi][ni], a[mi][0], a[mi][1], a[mi][2], a[mi][3], b0, b1);
            }
        }
        __syncthreads();
    }

    #pragma unroll
    for (int mi = 0; mi < 2; mi++) {
        int r = bm + wm + mi * 16 + g;
        #pragma unroll
        for (int ni = 0; ni < 8; ni++) {
            int c = bn + wn + ni * 8 + 2 * tg;
            *(float2*)(C + (size_t)r * N + c)       = make_float2(acc[mi][ni][0], acc[mi][ni][1]);
            *(float2*)(C + (size_t)(r + 8) * N + c) = make_float2(acc[mi][ni][2], acc[mi][ni][3]);
        }
    }
}

// ---------------- causal GQA flash attention (tf32 mma, fp32 softmax) ----------------
// grid: (T/128, NHEAD). 128 threads = 4 warps, each warp owns 32 query rows
// (two 16-row M tiles). Every K/V fragment load feeds 2 MMAs -> smem crossbar
// bytes per tile drop ~1.57x vs the 8-warp/16-row layout.
#define ATT_SMEM ((128*132 + 64*132 + 64*136 + 4*32*68) * 4)   // 171008 B

__global__ __launch_bounds__(128, 1) void attn_kernel(
    const float* __restrict__ qkv, float* __restrict__ out)
{
    extern __shared__ uint32_t sm[];
    uint32_t* Qs = sm;                   // [128][132]  tf32
    uint32_t* Ks = Qs + 128 * 132;       // [64][132]
    uint32_t* Vs = Ks + 64 * 132;        // [64][136]
    uint32_t* Ps = Vs + 64 * 136;        // per warp [32][68]

    const int qt  = gridDim.x - 1 - blockIdx.x;  // heavy tiles first
    const int h   = blockIdx.y;
    const int kvh = h >> 1;                      // G = 2
    const int tid = threadIdx.x, warp = tid >> 5, lane = tid & 31;
    const int g = lane >> 2, tg = lane & 3;
    const int q0 = qt << 7;
    const int wr = warp << 5;                    // 32 rows per warp
    uint32_t* Pw = Ps + warp * (32 * 68);

    {   // load Q tile (scaled) -> smem tf32 : 4096 float4 over 128 threads
        const float* qp = qkv + (size_t)q0 * QKV_N + h * HDIM;
        #pragma unroll
        for (int it = 0; it < 32; it++) {
            int i = tid + it * 128;
            int r = i >> 5, c = (i & 31) << 2;
            float4 v = *(const float4*)(qp + (size_t)r * QKV_N + c);
            *(uint4*)(Qs + r * 132 + c) = make_uint4(
                f2tf32(v.x * RSCALE), f2tf32(v.y * RSCALE),
                f2tf32(v.z * RSCALE), f2tf32(v.w * RSCALE));
        }
    }

    float O[2][16][4];
    #pragma unroll
    for (int mi = 0; mi < 2; mi++)
        #pragma unroll
        for (int ni = 0; ni < 16; ni++)
            #pragma unroll
            for (int c = 0; c < 4; c++) O[mi][ni][c] = 0.f;
    // row groups: 0:(wr+g) 1:(wr+8+g) 2:(wr+16+g) 3:(wr+24+g)
    float m[4] = {-1e30f, -1e30f, -1e30f, -1e30f};
    float l[4] = {0.f, 0.f, 0.f, 0.f};

    const int nkt = 2 * qt + 2;
    for (int kt = 0; kt < nkt; kt++) {
        const int k0 = kt << 6;
        __syncthreads();
        {   // stage K,V tiles: 2048 float4 each over 128 threads
            const float* kp = qkv + (size_t)k0 * QKV_N + QS + kvh * HDIM;
            const float* vp = qkv + (size_t)k0 * QKV_N + QS + KVS + kvh * HDIM;
            #pragma unroll
            for (int it = 0; it < 16; it++) {
                int i = tid + it * 128;
                int r = i >> 5, c = (i & 31) << 2;
                float4 kv = *(const float4*)(kp + (size_t)r * QKV_N + c);
                *(uint4*)(Ks + r * 132 + c) =
                    make_uint4(f2tf32(kv.x), f2tf32(kv.y), f2tf32(kv.z), f2tf32(kv.w));
                float4 vv = *(const float4*)(vp + (size_t)r * QKV_N + c);
                *(uint4*)(Vs + r * 136 + c) =
                    make_uint4(f2tf32(vv.x), f2tf32(vv.y), f2tf32(vv.z), f2tf32(vv.w));
            }
        }
        __syncthreads();

        // S[2][16 x 64] = Q_warp(32 rows) * K^T ; each K frag feeds 2 MMAs
        float S[2][8][4];
        #pragma unroll
        for (int mi = 0; mi < 2; mi++)
            #pragma unroll
            for (int ni = 0; ni < 8; ni++)
                #pragma unroll
                for (int c = 0; c < 4; c++) S[mi][ni][c] = 0.f;
        #pragma unroll
        for (int ks = 0; ks < 16; ks++) {
            uint32_t a[2][4];
            #pragma unroll
            for (int mi = 0; mi < 2; mi++) {
                const uint32_t* Ap = Qs + (wr + mi * 16) * 132 + ks * 8;
                a[mi][0] = Ap[g * 132 + tg];
                a[mi][1] = Ap[(g + 8) * 132 + tg];
                a[mi][2] = Ap[g * 132 + tg + 4];
                a[mi][3] = Ap[(g + 8) * 132 + tg + 4];
            }
            #pragma unroll
            for (int ni = 0; ni < 8; ni++) {
                uint32_t b0 = Ks[(ni * 8 + g) * 132 + ks * 8 + tg];
                uint32_t b1 = Ks[(ni * 8 + g) * 132 + ks * 8 + 4 + tg];
                #pragma unroll
                for (int mi = 0; mi < 2; mi++)
                    mma_tf32(S[mi][ni], a[mi][0], a[mi][1], a[mi][2], a[mi][3], b0, b1);
            }
        }

        if (kt >= 2 * qt) {   // only the last two tiles can cross the diagonal
            #pragma unroll
            for (int mi = 0; mi < 2; mi++) {
                int r0 = q0 + wr + mi * 16 + g, r1 = r0 + 8;
                #pragma unroll
                for (int ni = 0; ni < 8; ni++) {
                    int key = k0 + ni * 8 + 2 * tg;
                    if (key     > r0) S[mi][ni][0] = -1e30f;
                    if (key + 1 > r0) S[mi][ni][1] = -1e30f;
                    if (key     > r1) S[mi][ni][2] = -1e30f;
                    if (key + 1 > r1) S[mi][ni][3] = -1e30f;
                }
            }
        }

        // online softmax over 4 row groups
        float mx[4] = {-1e30f, -1e30f, -1e30f, -1e30f};
        #pragma unroll
        for (int mi = 0; mi < 2; mi++)
            #pragma unroll
            for (int ni = 0; ni < 8; ni++) {
                mx[mi * 2]     = fmaxf(mx[mi * 2],     fmaxf(S[mi][ni][0], S[mi][ni][1]));
                mx[mi * 2 + 1] = fmaxf(mx[mi * 2 + 1], fmaxf(S[mi][ni][2], S[mi][ni][3]));
            }
        #pragma unroll
        for (int gi = 0; gi < 4; gi++) {
            mx[gi] = fmaxf(mx[gi], __shfl_xor_sync(0xffffffffu, mx[gi], 1));
            mx[gi] = fmaxf(mx[gi], __shfl_xor_sync(0xffffffffu, mx[gi], 2));
        }

        float al[4];
        #pragma unroll
        for (int gi = 0; gi < 4; gi++) {
            float mn = fmaxf(m[gi], mx[gi]);
            al[gi] = __expf(m[gi] - mn);
            m[gi] = mn;
        }
        float s[4] = {0.f, 0.f, 0.f, 0.f};
        #pragma unroll
        for (int mi = 0; mi < 2; mi++)
            #pragma unroll
            for (int ni = 0; ni < 8; ni++) {
                S[mi][ni][0] = __expf(S[mi][ni][0] - m[mi * 2]);
                S[mi][ni][1] = __expf(S[mi][ni][1] - m[mi * 2]);
                S[mi][ni][2] = __expf(S[mi][ni][2] - m[mi * 2 + 1]);
                S[mi][ni][3] = __expf(S[mi][ni][3] - m[mi * 2 + 1]);
                s[mi * 2]     += S[mi][ni][0] + S[mi][ni][1];
                s[mi * 2 + 1] += S[mi][ni][2] + S[mi][ni][3];
            }
        #pragma unroll
        for (int gi = 0; gi < 4; gi++) {
            s[gi] += __shfl_xor_sync(0xffffffffu, s[gi], 1);
            s[gi] += __shfl_xor_sync(0xffffffffu, s[gi], 2);
            l[gi] = l[gi] * al[gi] + s[gi];
        }

        #pragma unroll
        for (int mi = 0; mi < 2; mi++)
            #pragma unroll
            for (int ni = 0; ni < 16; ni++) {
                O[mi][ni][0] *= al[mi * 2];     O[mi][ni][1] *= al[mi * 2];
                O[mi][ni][2] *= al[mi * 2 + 1]; O[mi][ni][3] *= al[mi * 2 + 1];
            }

        // P -> per-warp smem (tf32), 32 rows, A-fragment layout
        #pragma unroll
        for (int mi = 0; mi < 2; mi++)
            #pragma unroll
            for (int ni = 0; ni < 8; ni++) {
                uint32_t* pp = Pw + (mi * 16) * 68 + ni * 8 + 2 * tg;
                pp[g * 68]           = f2tf32(S[mi][ni][0]);
                pp[g * 68 + 1]       = f2tf32(S[mi][ni][1]);
                pp[(g + 8) * 68]     = f2tf32(S[mi][ni][2]);
                pp[(g + 8) * 68 + 1] = f2tf32(S[mi][ni][3]);
            }
        __syncwarp();

        // O += P * V ; each V frag feeds 2 MMAs
        #pragma unroll
        for (int ks = 0; ks < 8; ks++) {
            uint32_t a[2][4];
            #pragma unroll
            for (int mi = 0; mi < 2; mi++) {
                const uint32_t* Pp = Pw + (mi * 16) * 68 + ks * 8;
                a[mi][0] = Pp[g * 68 + tg];
                a[mi][1] = Pp[(g + 8) * 68 + tg];
                a[mi][2] = Pp[g * 68 + tg + 4];
                a[mi][3] = Pp[(g + 8) * 68 + tg + 4];
            }
            #pragma unroll
            for (int ni = 0; ni < 16; ni++) {
                uint32_t b0 = Vs[(ks * 8 + tg) * 136 + ni * 8 + g];
                uint32_t b1 = Vs[(ks * 8 + 4 + tg) * 136 + ni * 8 + g];
                #pragma unroll
                for (int mi = 0; mi < 2; mi++)
                    mma_tf32(O[mi][ni], a[mi][0], a[mi][1], a[mi][2], a[mi][3], b0, b1);
            }
        }
    }

    // normalize and write out (2 x 16 rows per warp)
    #pragma unroll
    for (int mi = 0; mi < 2; mi++) {
        float il0 = 1.f / l[mi * 2], il1 = 1.f / l[mi * 2 + 1];
        float* op = out + (size_t)(q0 + wr + mi * 16) * QS + h * HDIM;
        #pragma unroll
        for (int ni = 0; ni < 16; ni++) {
            int c = ni * 8 + 2 * tg;
            *(float2*)(op + (size_t)g * QS + c) =
                make_float2(O[mi][ni][0] * il0, O[mi][ni][1] * il0);
            *(float2*)(op + (size_t)(g + 8) * QS + c) =
                make_float2(O[mi][ni][2] * il1, O[mi][ni][3] * il1);
        }
    }
}

// ---------------- launcher ----------------
extern "C" void kernel_launch(void* const* d_in, const int* in_sizes, int n_in,
                              void* d_out, int out_size)
{
    const int*   positions = (const int*)d_in[0];
    const float* hidden    = (const float*)d_in[1];
    const float* w_qkv     = (const float*)d_in[2];
    const float* w_o       = (const float*)d_in[3];
    const float* qw        = (const float*)d_in[4];
    const float* kw        = (const float*)d_in[5];
    float*       out       = (float*)d_out;

    float *qkv, *att, *rope;
    cudaGetSymbolAddress((void**)&qkv,  g_qkv);
    cudaGetSymbolAddress((void**)&att,  g_att);
    cudaGetSymbolAddress((void**)&rope, g_rope);

    cudaFuncSetAttribute(attn_kernel,
                         cudaFuncAttributeMaxDynamicSharedMemorySize, ATT_SMEM);

    build_rope_kernel<<<(T_TOK * 64 + 255) / 256, 256>>>(rope, positions);

    // qkv = hidden @ w_qkv   [4096,2048]x[2048,4096]
    gemm_tf32_kernel<<<dim3(QKV_N / 128, T_TOK / 128), 256>>>(
        hidden, w_qkv, qkv, T_TOK, QKV_N, HID);

    norm_rope_kernel<<<dim3(T_TOK, NHEAD + NKVH), 128>>>(qkv, qw, kw, rope);

    attn_kernel<<<dim3(T_TOK / 128, NHEAD), 128, ATT_SMEM>>>(qkv, att);

    // out = att @ w_o   [4096,2048]x[2048,2048]
    gemm_tf32_kernel<<<dim3(HID / 128, T_TOK / 128), 256>>>(
        att, w_o, out, T_TOK, HID, QS);
}

// round 14
// speedup vs baseline: 1.2008x; 1.2008x over previous
#include <cuda_runtime.h>
#include <cuda_bf16.h>
#include <stdint.h>
#include <math.h>

// ---------------- problem constants ----------------
#define T_TOK 4096
#define HID   2048
#define NHEAD 16
#define NKVH  8
#define HDIM  128
#define QS    (NHEAD*HDIM)        // 2048
#define KVS   (NKVH*HDIM)         // 1024
#define QKV_N (QS + 2*KVS)        // 4096
#define RSCALE 0.08838834764831845f   // 128^-0.5

// ---------------- scratch (no allocations allowed) ----------------
__device__ float g_qkv[(size_t)T_TOK * QKV_N];   // 64 MB
__device__ float g_att[(size_t)T_TOK * QS];      // 32 MB
__device__ float g_rope[(size_t)T_TOK * HDIM];   // [t][0:64]=cos, [64:128]=sin

// ---------------- helpers ----------------
__device__ __forceinline__ uint32_t f2tf32(float f) {
    uint32_t u;
    asm("cvt.rna.tf32.f32 %0, %1;" : "=r"(u) : "f"(f));
    return u;
}

__device__ __forceinline__ void mma_tf32(float c[4],
    uint32_t a0, uint32_t a1, uint32_t a2, uint32_t a3,
    uint32_t b0, uint32_t b1)
{
    asm volatile(
        "mma.sync.aligned.m16n8k8.row.col.f32.tf32.tf32.f32 "
        "{%0,%1,%2,%3},{%4,%5,%6,%7},{%8,%9},{%0,%1,%2,%3};\n"
        : "+f"(c[0]), "+f"(c[1]), "+f"(c[2]), "+f"(c[3])
        : "r"(a0), "r"(a1), "r"(a2), "r"(a3), "r"(b0), "r"(b1));
}

// ---------------- RoPE cos/sin table ----------------
__global__ void build_rope_kernel(float* __restrict__ tab,
                                  const int* __restrict__ positions)
{
    int i = blockIdx.x * blockDim.x + threadIdx.x;
    if (i >= T_TOK * 64) return;
    int t = i >> 6, j = i & 63;
    float inv = 1.0f / powf(1.0e6f, (float)(2 * j) / 128.0f);
    float ang = (float)positions[t] * inv;
    tab[(size_t)t * 128 + j]      = (float)cos((double)ang);
    tab[(size_t)t * 128 + 64 + j] = (float)sin((double)ang);
}

// ---------------- fused per-head RMSNorm + RoPE (in place on q,k) ----------------
__global__ void norm_rope_kernel(float* __restrict__ qkv,
                                 const float* __restrict__ qw,
                                 const float* __restrict__ kw,
                                 const float* __restrict__ tab)
{
    int t  = blockIdx.x;
    int hh = blockIdx.y;
    bool isq = hh < NHEAD;
    float* x = qkv + (size_t)t * QKV_N + (isq ? hh * HDIM : QS + (hh - NHEAD) * HDIM);
    const float* w = isq ? qw : kw;

    __shared__ float buf[HDIM];
    __shared__ float red[4];
    int d = threadIdx.x;
    float v = x[d];
    float ss = v * v;
    #pragma unroll
    for (int o = 16; o; o >>= 1) ss += __shfl_xor_sync(0xffffffffu, ss, o);
    if ((d & 31) == 0) red[d >> 5] = ss;
    __syncthreads();
    float tot = red[0] + red[1] + red[2] + red[3];
    float r = rsqrtf(tot * (1.0f / HDIM) + 1e-6f);
    buf[d] = v * r * w[d];
    __syncthreads();
    if (d < 64) {
        float x1 = buf[d], x2 = buf[d + 64];
        float c = tab[(size_t)t * 128 + d];
        float s = tab[(size_t)t * 128 + 64 + d];
        x[d]      = x1 * c - x2 * s;
        x[d + 64] = x2 * c + x1 * s;
    }
}

// ---------------- tf32 tensor-core GEMM: C[M,N] = A[M,K] * B[K,N] ----------------
// Block 128x128x32, 256 threads, warp tile 32x64.
// Ping-pong double-buffered smem: ONE __syncthreads per K-step; next-tile LDGs
// issue before compute, STS into the alternate buffer after compute.
#define GEMM_AS_W   (128 * 36)              // A buffer words
#define GEMM_BS_W   (32 * 136)              // B buffer words
#define GEMM_BUF_W  (GEMM_AS_W + GEMM_BS_W) // 8960 words per stage
#define GEMM_SMEM   (GEMM_BUF_W * 2 * 4)    // 71680 B

__global__ __launch_bounds__(256) void gemm_tf32_kernel(
    const float* __restrict__ A, const float* __restrict__ B,
    float* __restrict__ C, int M, int N, int K)
{
    extern __shared__ uint32_t smg[];

    const int tid  = threadIdx.x;
    const int lane = tid & 31, warp = tid >> 5;
    const int g  = lane >> 2, tg = lane & 3;
    const int wm = (warp & 3) << 5;
    const int wn = (warp >> 2) << 6;
    const int bm = blockIdx.y << 7, bn = blockIdx.x << 7;

    int ar[4], ac[4], br[4], bc[4];
    #pragma unroll
    for (int it = 0; it < 4; it++) {
        int i = tid + it * 256;
        ar[it] = i >> 3;  ac[it] = (i & 7) << 2;
        br[it] = i >> 5;  bc[it] = (i & 31) << 2;
    }

    float acc[2][8][4];
    #pragma unroll
    for (int mi = 0; mi < 2; mi++)
        #pragma unroll
        for (int ni = 0; ni < 8; ni++)
            #pragma unroll
            for (int c = 0; c < 4; c++) acc[mi][ni][c] = 0.f;

    // prefetch tile 0 and stage into buffer 0
    float4 ra[4], rb[4];
    #pragma unroll
    for (int it = 0; it < 4; it++) {
        ra[it] = *(const float4*)(A + (size_t)(bm + ar[it]) * K + ac[it]);
        rb[it] = *(const float4*)(B + (size_t)br[it] * N + bn + bc[it]);
    }
    {
        uint32_t* As = smg;
        uint32_t* Bs = smg + GEMM_AS_W;
        #pragma unroll
        for (int it = 0; it < 4; it++) {
            *(uint4*)(As + ar[it] * 36 + ac[it]) = make_uint4(
                f2tf32(ra[it].x), f2tf32(ra[it].y), f2tf32(ra[it].z), f2tf32(ra[it].w));
            *(uint4*)(Bs + br[it] * 136 + bc[it]) = make_uint4(
                f2tf32(rb[it].x), f2tf32(rb[it].y), f2tf32(rb[it].z), f2tf32(rb[it].w));
        }
    }
    __syncthreads();

    const int nsteps = K >> 5;
    for (int ks = 0; ks < nsteps; ks++) {
        const uint32_t* As = smg + (ks & 1) * GEMM_BUF_W;
        const uint32_t* Bs = As + GEMM_AS_W;
        const bool more = (ks + 1) < nsteps;

        // issue next tile's global loads (overlap with MMAs below)
        if (more) {
            int k0 = (ks + 1) << 5;
            #pragma unroll
            for (int it = 0; it < 4; it++) {
                ra[it] = *(const float4*)(A + (size_t)(bm + ar[it]) * K + k0 + ac[it]);
                rb[it] = *(const float4*)(B + (size_t)(k0 + br[it]) * N + bn + bc[it]);
            }
        }

        #pragma unroll
        for (int kk = 0; kk < 4; kk++) {
            uint32_t a[2][4];
            #pragma unroll
            for (int mi = 0; mi < 2; mi++) {
                const uint32_t* Ap = As + (wm + mi * 16) * 36 + kk * 8;
                a[mi][0] = Ap[g * 36 + tg];
                a[mi][1] = Ap[(g + 8) * 36 + tg];
                a[mi][2] = Ap[g * 36 + tg + 4];
                a[mi][3] = Ap[(g + 8) * 36 + tg + 4];
            }
            #pragma unroll
            for (int ni = 0; ni < 8; ni++) {
                uint32_t b0 = Bs[(kk * 8 + tg) * 136 + wn + ni * 8 + g];
                uint32_t b1 = Bs[(kk * 8 + tg + 4) * 136 + wn + ni * 8 + g];
                #pragma unroll
                for (int mi = 0; mi < 2; mi++)
                    mma_tf32(acc[mi][ni], a[mi][0], a[mi][1], a[mi][2], a[mi][3], b0, b1);
            }
        }

        // stage next tile into the alternate buffer
        if (more) {
            uint32_t* An = smg + ((ks + 1) & 1) * GEMM_BUF_W;
            uint32_t* Bn = An + GEMM_AS_W;
            #pragma unroll
            for (int it = 0; it < 4; it++) {
                *(uint4*)(An + ar[it] * 36 + ac[it]) = make_uint4(
                    f2tf32(ra[it].x), f2tf32(ra[it].y), f2tf32(ra[it].z), f2tf32(ra[it].w));
                *(uint4*)(Bn + br[it] * 136 + bc[it]) = make_uint4(
                    f2tf32(rb[it].x), f2tf32(rb[it].y), f2tf32(rb[it].z), f2tf32(rb[it].w));
            }
        }
        __syncthreads();
    }

    #pragma unroll
    for (int mi = 0; mi < 2; mi++) {
        int r = bm + wm + mi * 16 + g;
        #pragma unroll
        for (int ni = 0; ni < 8; ni++) {
            int c = bn + wn + ni * 8 + 2 * tg;
            *(float2*)(C + (size_t)r * N + c)       = make_float2(acc[mi][ni][0], acc[mi][ni][1]);
            *(float2*)(C + (size_t)(r + 8) * N + c) = make_float2(acc[mi][ni][2], acc[mi][ni][3]);
        }
    }
}

// ---------------- causal GQA flash attention (tf32 mma, fp32 softmax) ----------------
// R7 design (best known): grid (T/128, NHEAD), 256 threads = 8 warps,
// 16 query rows per warp, KV tiles of 64 keys, diagonal tiles only masked.
#define ATT_SMEM ((128*132 + 64*132 + 64*136 + 8*16*68) * 4)   // 171008 B

__global__ __launch_bounds__(256, 1) void attn_kernel(
    const float* __restrict__ qkv, float* __restrict__ out)
{
    extern __shared__ uint32_t sm[];
    uint32_t* Qs = sm;                   // [128][132]  tf32
    uint32_t* Ks = Qs + 128 * 132;       // [64][132]
    uint32_t* Vs = Ks + 64 * 132;        // [64][136]
    uint32_t* Ps = Vs + 64 * 136;        // per warp [16][68]

    const int qt  = gridDim.x - 1 - blockIdx.x;  // heavy tiles first
    const int h   = blockIdx.y;
    const int kvh = h >> 1;                      // G = 2
    const int tid = threadIdx.x, warp = tid >> 5, lane = tid & 31;
    const int g = lane >> 2, tg = lane & 3;
    const int q0 = qt << 7;
    const int wr = warp << 4;
    uint32_t* Pw = Ps + warp * (16 * 68);

    {   // load Q tile (scaled) -> smem tf32
        const float* qp = qkv + (size_t)q0 * QKV_N + h * HDIM;
        #pragma unroll
        for (int it = 0; it < 16; it++) {
            int i = tid + it * 256;
            int r = i >> 5, c = (i & 31) << 2;
            float4 v = *(const float4*)(qp + (size_t)r * QKV_N + c);
            *(uint4*)(Qs + r * 132 + c) = make_uint4(
                f2tf32(v.x * RSCALE), f2tf32(v.y * RSCALE),
                f2tf32(v.z * RSCALE), f2tf32(v.w * RSCALE));
        }
    }

    float O[16][4];
    #pragma unroll
    for (int ni = 0; ni < 16; ni++)
        #pragma unroll
        for (int c = 0; c < 4; c++) O[ni][c] = 0.f;
    float m0 = -1e30f, m1 = -1e30f, l0 = 0.f, l1 = 0.f;

    const int nkt = 2 * qt + 2;
    for (int kt = 0; kt < nkt; kt++) {
        const int k0 = kt << 6;
        __syncthreads();
        {   // load K,V tiles (64 keys x 128) -> smem tf32
            const float* kp = qkv + (size_t)k0 * QKV_N + QS + kvh * HDIM;
            const float* vp = qkv + (size_t)k0 * QKV_N + QS + KVS + kvh * HDIM;
            #pragma unroll
            for (int it = 0; it < 8; it++) {
                int i = tid + it * 256;
                int r = i >> 5, c = (i & 31) << 2;
                float4 kv = *(const float4*)(kp + (size_t)r * QKV_N + c);
                *(uint4*)(Ks + r * 132 + c) =
                    make_uint4(f2tf32(kv.x), f2tf32(kv.y), f2tf32(kv.z), f2tf32(kv.w));
                float4 vv = *(const float4*)(vp + (size_t)r * QKV_N + c);
                *(uint4*)(Vs + r * 136 + c) =
                    make_uint4(f2tf32(vv.x), f2tf32(vv.y), f2tf32(vv.z), f2tf32(vv.w));
            }
        }
        __syncthreads();

        // S[16 x 64] = Q_warp * K^T
        float S[8][4];
        #pragma unroll
        for (int ni = 0; ni < 8; ni++)
            #pragma unroll
            for (int c = 0; c < 4; c++) S[ni][c] = 0.f;
        #pragma unroll
        for (int ks = 0; ks < 16; ks++) {
            uint32_t a0 = Qs[(wr + g) * 132 + ks * 8 + tg];
            uint32_t a1 = Qs[(wr + 8 + g) * 132 + ks * 8 + tg];
            uint32_t a2 = Qs[(wr + g) * 132 + ks * 8 + 4 + tg];
            uint32_t a3 = Qs[(wr + 8 + g) * 132 + ks * 8 + 4 + tg];
            #pragma unroll
            for (int ni = 0; ni < 8; ni++) {
                uint32_t b0 = Ks[(ni * 8 + g) * 132 + ks * 8 + tg];
                uint32_t b1 = Ks[(ni * 8 + g) * 132 + ks * 8 + 4 + tg];
                mma_tf32(S[ni], a0, a1, a2, a3, b0, b1);
            }
        }

        if (kt >= 2 * qt) {   // only the last two tiles can cross the diagonal
            int r0 = q0 + wr + g, r1 = r0 + 8;
            #pragma unroll
            for (int ni = 0; ni < 8; ni++) {
                int key = k0 + ni * 8 + 2 * tg;
                if (key     > r0) S[ni][0] = -1e30f;
                if (key + 1 > r0) S[ni][1] = -1e30f;
                if (key     > r1) S[ni][2] = -1e30f;
                if (key + 1 > r1) S[ni][3] = -1e30f;
            }
        }

        // online softmax (rows g and g+8; reduction across the quad)
        float mx0 = -1e30f, mx1 = -1e30f;
        #pragma unroll
        for (int ni = 0; ni < 8; ni++) {
            mx0 = fmaxf(mx0, fmaxf(S[ni][0], S[ni][1]));
            mx1 = fmaxf(mx1, fmaxf(S[ni][2], S[ni][3]));
        }
        mx0 = fmaxf(mx0, __shfl_xor_sync(0xffffffffu, mx0, 1));
        mx0 = fmaxf(mx0, __shfl_xor_sync(0xffffffffu, mx0, 2));
        mx1 = fmaxf(mx1, __shfl_xor_sync(0xffffffffu, mx1, 1));
        mx1 = fmaxf(mx1, __shfl_xor_sync(0xffffffffu, mx1, 2));

        float mn0 = fmaxf(m0, mx0), mn1 = fmaxf(m1, mx1);
        float al0 = __expf(m0 - mn0), al1 = __expf(m1 - mn1);
        float s0 = 0.f, s1 = 0.f;
        #pragma unroll
        for (int ni = 0; ni < 8; ni++) {
            S[ni][0] = __expf(S[ni][0] - mn0);
            S[ni][1] = __expf(S[ni][1] - mn0);
            S[ni][2] = __expf(S[ni][2] - mn1);
            S[ni][3] = __expf(S[ni][3] - mn1);
            s0 += S[ni][0] + S[ni][1];
            s1 += S[ni][2] + S[ni][3];
        }
        s0 += __shfl_xor_sync(0xffffffffu, s0, 1);
        s0 += __shfl_xor_sync(0xffffffffu, s0, 2);
        s1 += __shfl_xor_sync(0xffffffffu, s1, 1);
        s1 += __shfl_xor_sync(0xffffffffu, s1, 2);
        l0 = l0 * al0 + s0;
        l1 = l1 * al1 + s1;
        m0 = mn0; m1 = mn1;

        #pragma unroll
        for (int ni = 0; ni < 16; ni++) {
            O[ni][0] *= al0; O[ni][1] *= al0;
            O[ni][2] *= al1; O[ni][3] *= al1;
        }

        // P -> per-warp smem (tf32) to adopt the A-fragment layout
        #pragma unroll
        for (int ni = 0; ni < 8; ni++) {
            Pw[g * 68 + ni * 8 + 2 * tg]           = f2tf32(S[ni][0]);
            Pw[g * 68 + ni * 8 + 2 * tg + 1]       = f2tf32(S[ni][1]);
            Pw[(g + 8) * 68 + ni * 8 + 2 * tg]     = f2tf32(S[ni][2]);
            Pw[(g + 8) * 68 + ni * 8 + 2 * tg + 1] = f2tf32(S[ni][3]);
        }
        __syncwarp();

        // O += P * V
        #pragma unroll
        for (int ks = 0; ks < 8; ks++) {
            uint32_t a0 = Pw[g * 68 + ks * 8 + tg];
            uint32_t a1 = Pw[(g + 8) * 68 + ks * 8 + tg];
            uint32_t a2 = Pw[g * 68 + ks * 8 + 4 + tg];
            uint32_t a3 = Pw[(g + 8) * 68 + ks * 8 + 4 + tg];
            #pragma unroll
            for (int ni = 0; ni < 16; ni++) {
                uint32_t b0 = Vs[(ks * 8 + tg) * 136 + ni * 8 + g];
                uint32_t b1 = Vs[(ks * 8 + 4 + tg) * 136 + ni * 8 + g];
                mma_tf32(O[ni], a0, a1, a2, a3, b0, b1);
            }
        }
    }

    // normalize and write out
    float il0 = 1.f / l0, il1 = 1.f / l1;
    float* op = out + (size_t)(q0 + wr) * QS + h * HDIM;
    #pragma unroll
    for (int ni = 0; ni < 16; ni++) {
        int c = ni * 8 + 2 * tg;
        *(float2*)(op + (size_t)g * QS + c) =
            make_float2(O[ni][0] * il0, O[ni][1] * il0);
        *(float2*)(op + (size_t)(g + 8) * QS + c) =
            make_float2(O[ni][2] * il1, O[ni][3] * il1);
    }
}

// ---------------- launcher ----------------
extern "C" void kernel_launch(void* const* d_in, const int* in_sizes, int n_in,
                              void* d_out, int out_size)
{
    const int*   positions = (const int*)d_in[0];
    const float* hidden    = (const float*)d_in[1];
    const float* w_qkv     = (const float*)d_in[2];
    const float* w_o       = (const float*)d_in[3];
    const float* qw        = (const float*)d_in[4];
    const float* kw        = (const float*)d_in[5];
    float*       out       = (float*)d_out;

    float *qkv, *att, *rope;
    cudaGetSymbolAddress((void**)&qkv,  g_qkv);
    cudaGetSymbolAddress((void**)&att,  g_att);
    cudaGetSymbolAddress((void**)&rope, g_rope);

    cudaFuncSetAttribute(attn_kernel,
                         cudaFuncAttributeMaxDynamicSharedMemorySize, ATT_SMEM);
    cudaFuncSetAttribute(gemm_tf32_kernel,
                         cudaFuncAttributeMaxDynamicSharedMemorySize, GEMM_SMEM);

    build_rope_kernel<<<(T_TOK * 64 + 255) / 256, 256>>>(rope, positions);

    // qkv = hidden @ w_qkv   [4096,2048]x[2048,4096]
    gemm_tf32_kernel<<<dim3(QKV_N / 128, T_TOK / 128), 256, GEMM_SMEM>>>(
        hidden, w_qkv, qkv, T_TOK, QKV_N, HID);

    norm_rope_kernel<<<dim3(T_TOK, NHEAD + NKVH), 128>>>(qkv, qw, kw, rope);

    attn_kernel<<<dim3(T_TOK / 128, NHEAD), 256, ATT_SMEM>>>(qkv, att);

    // out = att @ w_o   [4096,2048]x[2048,2048]
    gemm_tf32_kernel<<<dim3(HID / 128, T_TOK / 128), 256, GEMM_SMEM>>>(
        att, w_o, out, T_TOK, HID, QS);
}

// round 15
// speedup vs baseline: 1.3746x; 1.1448x over previous
#include <cuda_runtime.h>
#include <cuda_bf16.h>
#include <stdint.h>
#include <math.h>

// ---------------- problem constants ----------------
#define T_TOK 4096
#define HID   2048
#define NHEAD 16
#define NKVH  8
#define HDIM  128
#define QS    (NHEAD*HDIM)        // 2048
#define KVS   (NKVH*HDIM)         // 1024
#define QKV_N (QS + 2*KVS)        // 4096
#define RSCALE 0.08838834764831845f   // 128^-0.5

// ---------------- scratch (no allocations allowed) ----------------
__device__ float g_qkv[(size_t)T_TOK * QKV_N];   // 64 MB
__device__ float g_att[(size_t)T_TOK * QS];      // 32 MB  (stored tf32-rounded)
__device__ float g_rope[(size_t)T_TOK * HDIM];   // [t][0:64]=cos, [64:128]=sin
__device__ float g_hid_t[(size_t)T_TOK * HID];   // 32 MB  tf32-rounded hidden
__device__ float g_wqkv_t[(size_t)HID * QKV_N];  // 32 MB  tf32-rounded w_qkv
__device__ float g_wo_t[(size_t)QS * HID];       // 16 MB  tf32-rounded w_o

// ---------------- helpers ----------------
__device__ __forceinline__ uint32_t f2tf32(float f) {
    uint32_t u;
    asm("cvt.rna.tf32.f32 %0, %1;" : "=r"(u) : "f"(f));
    return u;
}

__device__ __forceinline__ void mma_tf32(float c[4],
    uint32_t a0, uint32_t a1, uint32_t a2, uint32_t a3,
    uint32_t b0, uint32_t b1)
{
    asm volatile(
        "mma.sync.aligned.m16n8k8.row.col.f32.tf32.tf32.f32 "
        "{%0,%1,%2,%3},{%4,%5,%6,%7},{%8,%9},{%0,%1,%2,%3};\n"
        : "+f"(c[0]), "+f"(c[1]), "+f"(c[2]), "+f"(c[3])
        : "r"(a0), "r"(a1), "r"(a2), "r"(a3), "r"(b0), "r"(b1));
}

__device__ __forceinline__ uint32_t smem_u32(const void* p) {
    uint32_t a;
    asm("{ .reg .u64 t; cvta.to.shared.u64 t, %1; cvt.u32.u64 %0, t; }"
        : "=r"(a) : "l"(p));
    return a;
}

__device__ __forceinline__ void cp16(uint32_t saddr, const void* gaddr) {
    asm volatile("cp.async.cg.shared.global [%0], [%1], 16;"
                 :: "r"(saddr), "l"(gaddr));
}
#define CP_COMMIT() asm volatile("cp.async.commit_group;" ::: "memory")
#define CP_WAIT(n)  asm volatile("cp.async.wait_group %0;" :: "n"(n) : "memory")

// ---------------- tf32 pre-round (elementwise, float4) ----------------
__global__ void tf32_round_kernel(float* __restrict__ dst,
                                  const float* __restrict__ src, int n4)
{
    int i = blockIdx.x * blockDim.x + threadIdx.x;
    if (i >= n4) return;
    float4 v = ((const float4*)src)[i];
    ((uint4*)dst)[i] = make_uint4(f2tf32(v.x), f2tf32(v.y), f2tf32(v.z), f2tf32(v.w));
}

// ---------------- RoPE cos/sin table ----------------
__global__ void build_rope_kernel(float* __restrict__ tab,
                                  const int* __restrict__ positions)
{
    int i = blockIdx.x * blockDim.x + threadIdx.x;
    if (i >= T_TOK * 64) return;
    int t = i >> 6, j = i & 63;
    float inv = 1.0f / powf(1.0e6f, (float)(2 * j) / 128.0f);
    float ang = (float)positions[t] * inv;
    tab[(size_t)t * 128 + j]      = (float)cos((double)ang);
    tab[(size_t)t * 128 + 64 + j] = (float)sin((double)ang);
}

// ---------------- fused per-head RMSNorm + RoPE (in place on q,k) ----------------
__global__ void norm_rope_kernel(float* __restrict__ qkv,
                                 const float* __restrict__ qw,
                                 const float* __restrict__ kw,
                                 const float* __restrict__ tab)
{
    int t  = blockIdx.x;
    int hh = blockIdx.y;
    bool isq = hh < NHEAD;
    float* x = qkv + (size_t)t * QKV_N + (isq ? hh * HDIM : QS + (hh - NHEAD) * HDIM);
    const float* w = isq ? qw : kw;

    __shared__ float buf[HDIM];
    __shared__ float red[4];
    int d = threadIdx.x;
    float v = x[d];
    float ss = v * v;
    #pragma unroll
    for (int o = 16; o; o >>= 1) ss += __shfl_xor_sync(0xffffffffu, ss, o);
    if ((d & 31) == 0) red[d >> 5] = ss;
    __syncthreads();
    float tot = red[0] + red[1] + red[2] + red[3];
    float r = rsqrtf(tot * (1.0f / HDIM) + 1e-6f);
    buf[d] = v * r * w[d];
    __syncthreads();
    if (d < 64) {
        float x1 = buf[d], x2 = buf[d + 64];
        float c = tab[(size_t)t * 128 + d];
        float s = tab[(size_t)t * 128 + 64 + d];
        x[d]      = x1 * c - x2 * s;
        x[d + 64] = x2 * c + x1 * s;
    }
}

// ---------------- tf32 tensor-core GEMM: C[M,N] = A[M,K] * B[K,N] ----------------
// A and B are PRE-ROUNDED to tf32 (bit pattern in fp32). Block 128x128x32,
// 256 threads, warp tile 32x64. 2-stage cp.async pipeline; no staging regs,
// no in-loop cvt -> ~100 regs -> 2 CTAs/SM so CTAs overlap barriers/staging.
#define GEMM_AS_W   (128 * 36)
#define GEMM_BS_W   (32 * 136)
#define GEMM_BUF_W  (GEMM_AS_W + GEMM_BS_W)
#define GEMM_SMEM   (GEMM_BUF_W * 2 * 4)    // 71680 B

__global__ __launch_bounds__(256, 2) void gemm_tf32_kernel(
    const float* __restrict__ A, const float* __restrict__ B,
    float* __restrict__ C, int M, int N, int K)
{
    extern __shared__ uint32_t smg[];
    const uint32_t sbase = smem_u32(smg);

    const int tid  = threadIdx.x;
    const int lane = tid & 31, warp = tid >> 5;
    const int g  = lane >> 2, tg = lane & 3;
    const int wm = (warp & 3) << 5;
    const int wn = (warp >> 2) << 6;
    const int bm = blockIdx.y << 7, bn = blockIdx.x << 7;

    int ar[4], ac[4], br[4], bc[4];
    #pragma unroll
    for (int it = 0; it < 4; it++) {
        int i = tid + it * 256;
        ar[it] = i >> 3;  ac[it] = (i & 7) << 2;
        br[it] = i >> 5;  bc[it] = (i & 31) << 2;
    }

    float acc[2][8][4];
    #pragma unroll
    for (int mi = 0; mi < 2; mi++)
        #pragma unroll
        for (int ni = 0; ni < 8; ni++)
            #pragma unroll
            for (int c = 0; c < 4; c++) acc[mi][ni][c] = 0.f;

    // stage tile k0 into buffer s via cp.async
    auto stage = [&](int s, int k0) {
        uint32_t abase = sbase + (uint32_t)(s * GEMM_BUF_W) * 4u;
        uint32_t bbase = abase + (uint32_t)GEMM_AS_W * 4u;
        #pragma unroll
        for (int it = 0; it < 4; it++) {
            cp16(abase + (uint32_t)(ar[it] * 36 + ac[it]) * 4u,
                 A + (size_t)(bm + ar[it]) * K + k0 + ac[it]);
            cp16(bbase + (uint32_t)(br[it] * 136 + bc[it]) * 4u,
                 B + (size_t)(k0 + br[it]) * N + bn + bc[it]);
        }
        CP_COMMIT();
    };

    stage(0, 0);

    const int nsteps = K >> 5;
    for (int ks = 0; ks < nsteps; ks++) {
        const bool more = (ks + 1) < nsteps;
        if (more) {
            stage((ks + 1) & 1, (ks + 1) << 5);
            CP_WAIT(1);          // current buffer's group complete
        } else {
            CP_WAIT(0);
        }
        __syncthreads();

        const uint32_t* As = smg + (ks & 1) * GEMM_BUF_W;
        const uint32_t* Bs = As + GEMM_AS_W;

        #pragma unroll
        for (int kk = 0; kk < 4; kk++) {
            uint32_t a[2][4];
            #pragma unroll
            for (int mi = 0; mi < 2; mi++) {
                const uint32_t* Ap = As + (wm + mi * 16) * 36 + kk * 8;
                a[mi][0] = Ap[g * 36 + tg];
                a[mi][1] = Ap[(g + 8) * 36 + tg];
                a[mi][2] = Ap[g * 36 + tg + 4];
                a[mi][3] = Ap[(g + 8) * 36 + tg + 4];
            }
            #pragma unroll
            for (int ni = 0; ni < 8; ni++) {
                uint32_t b0 = Bs[(kk * 8 + tg) * 136 + wn + ni * 8 + g];
                uint32_t b1 = Bs[(kk * 8 + tg + 4) * 136 + wn + ni * 8 + g];
                #pragma unroll
                for (int mi = 0; mi < 2; mi++)
                    mma_tf32(acc[mi][ni], a[mi][0], a[mi][1], a[mi][2], a[mi][3], b0, b1);
            }
        }
        __syncthreads();   // WAR guard before buffer (ks&1) is restaged
    }

    #pragma unroll
    for (int mi = 0; mi < 2; mi++) {
        int r = bm + wm + mi * 16 + g;
        #pragma unroll
        for (int ni = 0; ni < 8; ni++) {
            int c = bn + wn + ni * 8 + 2 * tg;
            *(float2*)(C + (size_t)r * N + c)       = make_float2(acc[mi][ni][0], acc[mi][ni][1]);
            *(float2*)(C + (size_t)(r + 8) * N + c) = make_float2(acc[mi][ni][2], acc[mi][ni][3]);
        }
    }
}

// ---------------- causal GQA flash attention (tf32 mma, fp32 softmax) ----------------
// Reproducible 657us design: grid (T/128, NHEAD), 256 threads = 8 warps,
// 16 query rows per warp, KV tiles of 64 keys. Output stored tf32-rounded
// (same rounding the O-proj GEMM used to apply -> bit-identical pipeline).
#define ATT_SMEM ((128*132 + 64*132 + 64*136 + 8*16*68) * 4)   // 171008 B

__global__ __launch_bounds__(256, 1) void attn_kernel(
    const float* __restrict__ qkv, float* __restrict__ out)
{
    extern __shared__ uint32_t sm[];
    uint32_t* Qs = sm;                   // [128][132]  tf32
    uint32_t* Ks = Qs + 128 * 132;       // [64][132]
    uint32_t* Vs = Ks + 64 * 132;        // [64][136]
    uint32_t* Ps = Vs + 64 * 136;        // per warp [16][68]

    const int qt  = gridDim.x - 1 - blockIdx.x;  // heavy tiles first
    const int h   = blockIdx.y;
    const int kvh = h >> 1;                      // G = 2
    const int tid = threadIdx.x, warp = tid >> 5, lane = tid & 31;
    const int g = lane >> 2, tg = lane & 3;
    const int q0 = qt << 7;
    const int wr = warp << 4;
    uint32_t* Pw = Ps + warp * (16 * 68);

    {   // load Q tile (scaled) -> smem tf32
        const float* qp = qkv + (size_t)q0 * QKV_N + h * HDIM;
        #pragma unroll
        for (int it = 0; it < 16; it++) {
            int i = tid + it * 256;
            int r = i >> 5, c = (i & 31) << 2;
            float4 v = *(const float4*)(qp + (size_t)r * QKV_N + c);
            *(uint4*)(Qs + r * 132 + c) = make_uint4(
                f2tf32(v.x * RSCALE), f2tf32(v.y * RSCALE),
                f2tf32(v.z * RSCALE), f2tf32(v.w * RSCALE));
        }
    }

    float O[16][4];
    #pragma unroll
    for (int ni = 0; ni < 16; ni++)
        #pragma unroll
        for (int c = 0; c < 4; c++) O[ni][c] = 0.f;
    float m0 = -1e30f, m1 = -1e30f, l0 = 0.f, l1 = 0.f;

    const int nkt = 2 * qt + 2;
    for (int kt = 0; kt < nkt; kt++) {
        const int k0 = kt << 6;
        __syncthreads();
        {   // load K,V tiles (64 keys x 128) -> smem tf32
            const float* kp = qkv + (size_t)k0 * QKV_N + QS + kvh * HDIM;
            const float* vp = qkv + (size_t)k0 * QKV_N + QS + KVS + kvh * HDIM;
            #pragma unroll
            for (int it = 0; it < 8; it++) {
                int i = tid + it * 256;
                int r = i >> 5, c = (i & 31) << 2;
                float4 kv = *(const float4*)(kp + (size_t)r * QKV_N + c);
                *(uint4*)(Ks + r * 132 + c) =
                    make_uint4(f2tf32(kv.x), f2tf32(kv.y), f2tf32(kv.z), f2tf32(kv.w));
                float4 vv = *(const float4*)(vp + (size_t)r * QKV_N + c);
                *(uint4*)(Vs + r * 136 + c) =
                    make_uint4(f2tf32(vv.x), f2tf32(vv.y), f2tf32(vv.z), f2tf32(vv.w));
            }
        }
        __syncthreads();

        // S[16 x 64] = Q_warp * K^T
        float S[8][4];
        #pragma unroll
        for (int ni = 0; ni < 8; ni++)
            #pragma unroll
            for (int c = 0; c < 4; c++) S[ni][c] = 0.f;
        #pragma unroll
        for (int ks = 0; ks < 16; ks++) {
            uint32_t a0 = Qs[(wr + g) * 132 + ks * 8 + tg];
            uint32_t a1 = Qs[(wr + 8 + g) * 132 + ks * 8 + tg];
            uint32_t a2 = Qs[(wr + g) * 132 + ks * 8 + 4 + tg];
            uint32_t a3 = Qs[(wr + 8 + g) * 132 + ks * 8 + 4 + tg];
            #pragma unroll
            for (int ni = 0; ni < 8; ni++) {
                uint32_t b0 = Ks[(ni * 8 + g) * 132 + ks * 8 + tg];
                uint32_t b1 = Ks[(ni * 8 + g) * 132 + ks * 8 + 4 + tg];
                mma_tf32(S[ni], a0, a1, a2, a3, b0, b1);
            }
        }

        if (kt >= 2 * qt) {   // only the last two tiles can cross the diagonal
            int r0 = q0 + wr + g, r1 = r0 + 8;
            #pragma unroll
            for (int ni = 0; ni < 8; ni++) {
                int key = k0 + ni * 8 + 2 * tg;
                if (key     > r0) S[ni][0] = -1e30f;
                if (key + 1 > r0) S[ni][1] = -1e30f;
                if (key     > r1) S[ni][2] = -1e30f;
                if (key + 1 > r1) S[ni][3] = -1e30f;
            }
        }

        // online softmax (rows g and g+8; reduction across the quad)
        float mx0 = -1e30f, mx1 = -1e30f;
        #pragma unroll
        for (int ni = 0; ni < 8; ni++) {
            mx0 = fmaxf(mx0, fmaxf(S[ni][0], S[ni][1]));
            mx1 = fmaxf(mx1, fmaxf(S[ni][2], S[ni][3]));
        }
        mx0 = fmaxf(mx0, __shfl_xor_sync(0xffffffffu, mx0, 1));
        mx0 = fmaxf(mx0, __shfl_xor_sync(0xffffffffu, mx0, 2));
        mx1 = fmaxf(mx1, __shfl_xor_sync(0xffffffffu, mx1, 1));
        mx1 = fmaxf(mx1, __shfl_xor_sync(0xffffffffu, mx1, 2));

        float mn0 = fmaxf(m0, mx0), mn1 = fmaxf(m1, mx1);
        float al0 = __expf(m0 - mn0), al1 = __expf(m1 - mn1);
        float s0 = 0.f, s1 = 0.f;
        #pragma unroll
        for (int ni = 0; ni < 8; ni++) {
            S[ni][0] = __expf(S[ni][0] - mn0);
            S[ni][1] = __expf(S[ni][1] - mn0);
            S[ni][2] = __expf(S[ni][2] - mn1);
            S[ni][3] = __expf(S[ni][3] - mn1);
            s0 += S[ni][0] + S[ni][1];
            s1 += S[ni][2] + S[ni][3];
        }
        s0 += __shfl_xor_sync(0xffffffffu, s0, 1);
        s0 += __shfl_xor_sync(0xffffffffu, s0, 2);
        s1 += __shfl_xor_sync(0xffffffffu, s1, 1);
        s1 += __shfl_xor_sync(0xffffffffu, s1, 2);
        l0 = l0 * al0 + s0;
        l1 = l1 * al1 + s1;
        m0 = mn0; m1 = mn1;

        #pragma unroll
        for (int ni = 0; ni < 16; ni++) {
            O[ni][0] *= al0; O[ni][1] *= al0;
            O[ni][2] *= al1; O[ni][3] *= al1;
        }

        // P -> per-warp smem (tf32) to adopt the A-fragment layout
        #pragma unroll
        for (int ni = 0; ni < 8; ni++) {
            Pw[g * 68 + ni * 8 + 2 * tg]           = f2tf32(S[ni][0]);
            Pw[g * 68 + ni * 8 + 2 * tg + 1]       = f2tf32(S[ni][1]);
            Pw[(g + 8) * 68 + ni * 8 + 2 * tg]     = f2tf32(S[ni][2]);
            Pw[(g + 8) * 68 + ni * 8 + 2 * tg + 1] = f2tf32(S[ni][3]);
        }
        __syncwarp();

        // O += P * V
        #pragma unroll
        for (int ks = 0; ks < 8; ks++) {
            uint32_t a0 = Pw[g * 68 + ks * 8 + tg];
            uint32_t a1 = Pw[(g + 8) * 68 + ks * 8 + tg];
            uint32_t a2 = Pw[g * 68 + ks * 8 + 4 + tg];
            uint32_t a3 = Pw[(g + 8) * 68 + ks * 8 + 4 + tg];
            #pragma unroll
            for (int ni = 0; ni < 16; ni++) {
                uint32_t b0 = Vs[(ks * 8 + tg) * 136 + ni * 8 + g];
                uint32_t b1 = Vs[(ks * 8 + 4 + tg) * 136 + ni * 8 + g];
                mma_tf32(O[ni], a0, a1, a2, a3, b0, b1);
            }
        }
    }

    // normalize and write out, tf32-rounded for the O-proj GEMM
    float il0 = 1.f / l0, il1 = 1.f / l1;
    float* op = out + (size_t)(q0 + wr) * QS + h * HDIM;
    #pragma unroll
    for (int ni = 0; ni < 16; ni++) {
        int c = ni * 8 + 2 * tg;
        *(uint2*)(op + (size_t)g * QS + c) =
            make_uint2(f2tf32(O[ni][0] * il0), f2tf32(O[ni][1] * il0));
        *(uint2*)(op + (size_t)(g + 8) * QS + c) =
            make_uint2(f2tf32(O[ni][2] * il1), f2tf32(O[ni][3] * il1));
    }
}

// ---------------- launcher ----------------
extern "C" void kernel_launch(void* const* d_in, const int* in_sizes, int n_in,
                              void* d_out, int out_size)
{
    const int*   positions = (const int*)d_in[0];
    const float* hidden    = (const float*)d_in[1];
    const float* w_qkv     = (const float*)d_in[2];
    const float* w_o       = (const float*)d_in[3];
    const float* qw        = (const float*)d_in[4];
    const float* kw        = (const float*)d_in[5];
    float*       out       = (float*)d_out;

    float *qkv, *att, *rope, *hid_t, *wqkv_t, *wo_t;
    cudaGetSymbolAddress((void**)&qkv,    g_qkv);
    cudaGetSymbolAddress((void**)&att,    g_att);
    cudaGetSymbolAddress((void**)&rope,   g_rope);
    cudaGetSymbolAddress((void**)&hid_t,  g_hid_t);
    cudaGetSymbolAddress((void**)&wqkv_t, g_wqkv_t);
    cudaGetSymbolAddress((void**)&wo_t,   g_wo_t);

    cudaFuncSetAttribute(attn_kernel,
                         cudaFuncAttributeMaxDynamicSharedMemorySize, ATT_SMEM);
    cudaFuncSetAttribute(gemm_tf32_kernel,
                         cudaFuncAttributeMaxDynamicSharedMemorySize, GEMM_SMEM);

    // pre-round GEMM inputs to tf32 (same cvt.rna the GEMM used to do in-loop)
    {
        int n4;
        n4 = (T_TOK * HID) / 4;
        tf32_round_kernel<<<(n4 + 255) / 256, 256>>>(hid_t, hidden, n4);
        n4 = (HID * QKV_N) / 4;
        tf32_round_kernel<<<(n4 + 255) / 256, 256>>>(wqkv_t, w_qkv, n4);
        n4 = (QS * HID) / 4;
        tf32_round_kernel<<<(n4 + 255) / 256, 256>>>(wo_t, w_o, n4);
    }

    build_rope_kernel<<<(T_TOK * 64 + 255) / 256, 256>>>(rope, positions);

    // qkv = hidden @ w_qkv   [4096,2048]x[2048,4096]
    gemm_tf32_kernel<<<dim3(QKV_N / 128, T_TOK / 128), 256, GEMM_SMEM>>>(
        hid_t, wqkv_t, qkv, T_TOK, QKV_N, HID);

    norm_rope_kernel<<<dim3(T_TOK, NHEAD + NKVH), 128>>>(qkv, qw, kw, rope);

    attn_kernel<<<dim3(T_TOK / 128, NHEAD), 256, ATT_SMEM>>>(qkv, att);

    // out = att @ w_o   [4096,2048]x[2048,2048]
    gemm_tf32_kernel<<<dim3(HID / 128, T_TOK / 128), 256, GEMM_SMEM>>>(
        att, wo_t, out, T_TOK, HID, QS);
}

// round 16
// speedup vs baseline: 1.3886x; 1.0102x over previous
#include <cuda_runtime.h>
#include <cuda_bf16.h>
#include <stdint.h>
#include <math.h>

// ---------------- problem constants ----------------
#define T_TOK 4096
#define HID   2048
#define NHEAD 16
#define NKVH  8
#define HDIM  128
#define QS    (NHEAD*HDIM)        // 2048
#define KVS   (NKVH*HDIM)         // 1024
#define QKV_N (QS + 2*KVS)        // 4096
#define RSCALE 0.08838834764831845f   // 128^-0.5

// ---------------- scratch (no allocations allowed) ----------------
__device__ float g_qkv[(size_t)T_TOK * QKV_N];   // 64 MB (q,k,v tf32-rounded post norm_rope)
__device__ float g_att[(size_t)T_TOK * QS];      // 32 MB (stored tf32-rounded)
__device__ float g_rope[(size_t)T_TOK * HDIM];   // [t][0:64]=cos, [64:128]=sin
__device__ float g_hid_t[(size_t)T_TOK * HID];   // tf32-rounded hidden
__device__ float g_wqkv_t[(size_t)HID * QKV_N];  // tf32-rounded w_qkv
__device__ float g_wo_t[(size_t)QS * HID];       // tf32-rounded w_o

// ---------------- helpers ----------------
__device__ __forceinline__ uint32_t f2tf32(float f) {
    uint32_t u;
    asm("cvt.rna.tf32.f32 %0, %1;" : "=r"(u) : "f"(f));
    return u;
}

__device__ __forceinline__ void mma_tf32(float c[4],
    uint32_t a0, uint32_t a1, uint32_t a2, uint32_t a3,
    uint32_t b0, uint32_t b1)
{
    asm volatile(
        "mma.sync.aligned.m16n8k8.row.col.f32.tf32.tf32.f32 "
        "{%0,%1,%2,%3},{%4,%5,%6,%7},{%8,%9},{%0,%1,%2,%3};\n"
        : "+f"(c[0]), "+f"(c[1]), "+f"(c[2]), "+f"(c[3])
        : "r"(a0), "r"(a1), "r"(a2), "r"(a3), "r"(b0), "r"(b1));
}

__device__ __forceinline__ uint32_t smem_u32(const void* p) {
    uint32_t a;
    asm("{ .reg .u64 t; cvta.to.shared.u64 t, %1; cvt.u32.u64 %0, t; }"
        : "=r"(a) : "l"(p));
    return a;
}

__device__ __forceinline__ void cp16(uint32_t saddr, const void* gaddr) {
    asm volatile("cp.async.cg.shared.global [%0], [%1], 16;"
                 :: "r"(saddr), "l"(gaddr));
}
#define CP_COMMIT() asm volatile("cp.async.commit_group;" ::: "memory")
#define CP_WAIT(n)  asm volatile("cp.async.wait_group %0;" :: "n"(n) : "memory")

// ---------------- tf32 pre-round (elementwise, float4) ----------------
__global__ void tf32_round_kernel(float* __restrict__ dst,
                                  const float* __restrict__ src, int n4)
{
    int i = blockIdx.x * blockDim.x + threadIdx.x;
    if (i >= n4) return;
    float4 v = ((const float4*)src)[i];
    ((uint4*)dst)[i] = make_uint4(f2tf32(v.x), f2tf32(v.y), f2tf32(v.z), f2tf32(v.w));
}

// ---------------- RoPE cos/sin table ----------------
__global__ void build_rope_kernel(float* __restrict__ tab,
                                  const int* __restrict__ positions)
{
    int i = blockIdx.x * blockDim.x + threadIdx.x;
    if (i >= T_TOK * 64) return;
    int t = i >> 6, j = i & 63;
    float inv = 1.0f / powf(1.0e6f, (float)(2 * j) / 128.0f);
    float ang = (float)positions[t] * inv;
    tab[(size_t)t * 128 + j]      = (float)cos((double)ang);
    tab[(size_t)t * 128 + 64 + j] = (float)sin((double)ang);
}

// ---------------- fused per-head RMSNorm + RoPE + tf32 round (in place) ----------------
// grid: (T, 32). y: 0..15 q heads (scaled by RSCALE), 16..23 k heads, 24..31 v heads.
// Outputs are tf32 bit patterns so attention can cp.async them directly.
__global__ void norm_rope_kernel(float* __restrict__ qkv,
                                 const float* __restrict__ qw,
                                 const float* __restrict__ kw,
                                 const float* __restrict__ tab)
{
    int t  = blockIdx.x;
    int hh = blockIdx.y;
    int d  = threadIdx.x;

    if (hh >= NHEAD + NKVH) {            // v head: round only
        float* x = qkv + (size_t)t * QKV_N + QS + KVS + (hh - NHEAD - NKVH) * HDIM;
        x[d] = __uint_as_float(f2tf32(x[d]));
        return;
    }

    bool isq = hh < NHEAD;
    float* x = qkv + (size_t)t * QKV_N + (isq ? hh * HDIM : QS + (hh - NHEAD) * HDIM);
    const float* w = isq ? qw : kw;
    const float sc = isq ? RSCALE : 1.0f;

    __shared__ float buf[HDIM];
    __shared__ float red[4];
    float v = x[d];
    float ss = v * v;
    #pragma unroll
    for (int o = 16; o; o >>= 1) ss += __shfl_xor_sync(0xffffffffu, ss, o);
    if ((d & 31) == 0) red[d >> 5] = ss;
    __syncthreads();
    float tot = red[0] + red[1] + red[2] + red[3];
    float r = rsqrtf(tot * (1.0f / HDIM) + 1e-6f);
    buf[d] = v * r * w[d];
    __syncthreads();
    if (d < 64) {
        float x1 = buf[d], x2 = buf[d + 64];
        float c = tab[(size_t)t * 128 + d];
        float s = tab[(size_t)t * 128 + 64 + d];
        x[d]      = __uint_as_float(f2tf32((x1 * c - x2 * s) * sc));
        x[d + 64] = __uint_as_float(f2tf32((x2 * c + x1 * s) * sc));
    }
}

// ---------------- tf32 tensor-core GEMM: C[M,N] = A[M,K] * B[K,N] ----------------
// R15 version (WIN): pre-rounded inputs, 2-stage cp.async, 2 CTAs/SM.
#define GEMM_AS_W   (128 * 36)
#define GEMM_BS_W   (32 * 136)
#define GEMM_BUF_W  (GEMM_AS_W + GEMM_BS_W)
#define GEMM_SMEM   (GEMM_BUF_W * 2 * 4)    // 71680 B

__global__ __launch_bounds__(256, 2) void gemm_tf32_kernel(
    const float* __restrict__ A, const float* __restrict__ B,
    float* __restrict__ C, int M, int N, int K)
{
    extern __shared__ uint32_t smg[];
    const uint32_t sbase = smem_u32(smg);

    const int tid  = threadIdx.x;
    const int lane = tid & 31, warp = tid >> 5;
    const int g  = lane >> 2, tg = lane & 3;
    const int wm = (warp & 3) << 5;
    const int wn = (warp >> 2) << 6;
    const int bm = blockIdx.y << 7, bn = blockIdx.x << 7;

    int ar[4], ac[4], br[4], bc[4];
    #pragma unroll
    for (int it = 0; it < 4; it++) {
        int i = tid + it * 256;
        ar[it] = i >> 3;  ac[it] = (i & 7) << 2;
        br[it] = i >> 5;  bc[it] = (i & 31) << 2;
    }

    float acc[2][8][4];
    #pragma unroll
    for (int mi = 0; mi < 2; mi++)
        #pragma unroll
        for (int ni = 0; ni < 8; ni++)
            #pragma unroll
            for (int c = 0; c < 4; c++) acc[mi][ni][c] = 0.f;

    auto stage = [&](int s, int k0) {
        uint32_t abase = sbase + (uint32_t)(s * GEMM_BUF_W) * 4u;
        uint32_t bbase = abase + (uint32_t)GEMM_AS_W * 4u;
        #pragma unroll
        for (int it = 0; it < 4; it++) {
            cp16(abase + (uint32_t)(ar[it] * 36 + ac[it]) * 4u,
                 A + (size_t)(bm + ar[it]) * K + k0 + ac[it]);
            cp16(bbase + (uint32_t)(br[it] * 136 + bc[it]) * 4u,
                 B + (size_t)(k0 + br[it]) * N + bn + bc[it]);
        }
        CP_COMMIT();
    };

    stage(0, 0);

    const int nsteps = K >> 5;
    for (int ks = 0; ks < nsteps; ks++) {
        const bool more = (ks + 1) < nsteps;
        if (more) {
            stage((ks + 1) & 1, (ks + 1) << 5);
            CP_WAIT(1);
        } else {
            CP_WAIT(0);
        }
        __syncthreads();

        const uint32_t* As = smg + (ks & 1) * GEMM_BUF_W;
        const uint32_t* Bs = As + GEMM_AS_W;

        #pragma unroll
        for (int kk = 0; kk < 4; kk++) {
            uint32_t a[2][4];
            #pragma unroll
            for (int mi = 0; mi < 2; mi++) {
                const uint32_t* Ap = As + (wm + mi * 16) * 36 + kk * 8;
                a[mi][0] = Ap[g * 36 + tg];
                a[mi][1] = Ap[(g + 8) * 36 + tg];
                a[mi][2] = Ap[g * 36 + tg + 4];
                a[mi][3] = Ap[(g + 8) * 36 + tg + 4];
            }
            #pragma unroll
            for (int ni = 0; ni < 8; ni++) {
                uint32_t b0 = Bs[(kk * 8 + tg) * 136 + wn + ni * 8 + g];
                uint32_t b1 = Bs[(kk * 8 + tg + 4) * 136 + wn + ni * 8 + g];
                #pragma unroll
                for (int mi = 0; mi < 2; mi++)
                    mma_tf32(acc[mi][ni], a[mi][0], a[mi][1], a[mi][2], a[mi][3], b0, b1);
            }
        }
        __syncthreads();
    }

    #pragma unroll
    for (int mi = 0; mi < 2; mi++) {
        int r = bm + wm + mi * 16 + g;
        #pragma unroll
        for (int ni = 0; ni < 8; ni++) {
            int c = bn + wn + ni * 8 + 2 * tg;
            *(float2*)(C + (size_t)r * N + c)       = make_float2(acc[mi][ni][0], acc[mi][ni][1]);
            *(float2*)(C + (size_t)(r + 8) * N + c) = make_float2(acc[mi][ni][2], acc[mi][ni][3]);
        }
    }
}

// ---------------- causal GQA flash attention (tf32 mma, fp32 softmax) ----------------
// grid (T/128, NHEAD), 256 threads = 8 warps, 16 q rows/warp, 64-key KV tiles.
// All staging via cp.async (inputs pre-rounded tf32 in gmem); K double-buffered.
#define ATT_Q_W   (128 * 132)
#define ATT_K_W   (64 * 132)          // per stage
#define ATT_V_W   (64 * 136)
#define ATT_P_W   (8 * 16 * 68)
#define ATT_SMEM  ((ATT_Q_W + 2 * ATT_K_W + ATT_V_W + ATT_P_W) * 4)   // 204800 B

__global__ __launch_bounds__(256, 1) void attn_kernel(
    const float* __restrict__ qkv, float* __restrict__ out)
{
    extern __shared__ uint32_t sm[];
    uint32_t* Qs = sm;                       // [128][132]
    uint32_t* Kb = sm + ATT_Q_W;             // [2][64][132]
    uint32_t* Vs = Kb + 2 * ATT_K_W;         // [64][136]
    uint32_t* Ps = Vs + ATT_V_W;             // per warp [16][68]
    const uint32_t sbase = smem_u32(sm);

    const int qt  = gridDim.x - 1 - blockIdx.x;  // heavy tiles first
    const int h   = blockIdx.y;
    const int kvh = h >> 1;                      // G = 2
    const int tid = threadIdx.x, warp = tid >> 5, lane = tid & 31;
    const int g = lane >> 2, tg = lane & 3;
    const int q0 = qt << 7;
    const int wr = warp << 4;
    uint32_t* Pw = Ps + warp * (16 * 68);

    const float* kbase = qkv + QS + kvh * HDIM;
    const float* vbase = qkv + QS + KVS + kvh * HDIM;

    // ---- prologue: async-stage Q, K0, V0 ----
    {
        const float* qp = qkv + (size_t)q0 * QKV_N + h * HDIM;
        #pragma unroll
        for (int it = 0; it < 16; it++) {
            int i = tid + it * 256;
            int r = i >> 5, c = (i & 31) << 2;
            cp16(sbase + (uint32_t)(r * 132 + c) * 4u, qp + (size_t)r * QKV_N + c);
        }
        CP_COMMIT();
        #pragma unroll
        for (int it = 0; it < 8; it++) {
            int i = tid + it * 256;
            int r = i >> 5, c = (i & 31) << 2;
            cp16(sbase + (uint32_t)(ATT_Q_W + r * 132 + c) * 4u,
                 kbase + (size_t)r * QKV_N + c);
        }
        CP_COMMIT();
        #pragma unroll
        for (int it = 0; it < 8; it++) {
            int i = tid + it * 256;
            int r = i >> 5, c = (i & 31) << 2;
            cp16(sbase + (uint32_t)(ATT_Q_W + 2 * ATT_K_W + r * 136 + c) * 4u,
                 vbase + (size_t)r * QKV_N + c);
        }
        CP_COMMIT();
    }

    float O[16][4];
    #pragma unroll
    for (int ni = 0; ni < 16; ni++)
        #pragma unroll
        for (int c = 0; c < 4; c++) O[ni][c] = 0.f;
    float m0 = -1e30f, m1 = -1e30f, l0 = 0.f, l1 = 0.f;

    const int nkt = 2 * qt + 2;
    for (int kt = 0; kt < nkt; kt++) {
        const bool more = (kt + 1) < nkt;

        // K(kt) ready (queue head); Q also drains on kt==0
        CP_WAIT(1);
        __syncthreads();

        const uint32_t* Ks = Kb + (kt & 1) * ATT_K_W;

        // S[16 x 64] = Q_warp * K^T
        float S[8][4];
        #pragma unroll
        for (int ni = 0; ni < 8; ni++)
            #pragma unroll
            for (int c = 0; c < 4; c++) S[ni][c] = 0.f;
        #pragma unroll
        for (int ks = 0; ks < 16; ks++) {
            uint32_t a0 = Qs[(wr + g) * 132 + ks * 8 + tg];
            uint32_t a1 = Qs[(wr + 8 + g) * 132 + ks * 8 + tg];
            uint32_t a2 = Qs[(wr + g) * 132 + ks * 8 + 4 + tg];
            uint32_t a3 = Qs[(wr + 8 + g) * 132 + ks * 8 + 4 + tg];
            #pragma unroll
            for (int ni = 0; ni < 8; ni++) {
                uint32_t b0 = Ks[(ni * 8 + g) * 132 + ks * 8 + tg];
                uint32_t b1 = Ks[(ni * 8 + g) * 132 + ks * 8 + 4 + tg];
                mma_tf32(S[ni], a0, a1, a2, a3, b0, b1);
            }
        }

        // prefetch K(kt+1) into the other K buffer (safe: all warps past barrier)
        if (more) {
            const float* kp = kbase + (size_t)((kt + 1) << 6) * QKV_N;
            uint32_t kb = sbase + (uint32_t)(ATT_Q_W + ((kt + 1) & 1) * ATT_K_W) * 4u;
            #pragma unroll
            for (int it = 0; it < 8; it++) {
                int i = tid + it * 256;
                int r = i >> 5, c = (i & 31) << 2;
                cp16(kb + (uint32_t)(r * 132 + c) * 4u, kp + (size_t)r * QKV_N + c);
            }
            CP_COMMIT();
        }

        const int k0 = kt << 6;
        if (kt >= 2 * qt) {   // only the last two tiles can cross the diagonal
            int r0 = q0 + wr + g, r1 = r0 + 8;
            #pragma unroll
            for (int ni = 0; ni < 8; ni++) {
                int key = k0 + ni * 8 + 2 * tg;
                if (key     > r0) S[ni][0] = -1e30f;
                if (key + 1 > r0) S[ni][1] = -1e30f;
                if (key     > r1) S[ni][2] = -1e30f;
                if (key + 1 > r1) S[ni][3] = -1e30f;
            }
        }

        // online softmax (rows g and g+8; reduction across the quad)
        float mx0 = -1e30f, mx1 = -1e30f;
        #pragma unroll
        for (int ni = 0; ni < 8; ni++) {
            mx0 = fmaxf(mx0, fmaxf(S[ni][0], S[ni][1]));
            mx1 = fmaxf(mx1, fmaxf(S[ni][2], S[ni][3]));
        }
        mx0 = fmaxf(mx0, __shfl_xor_sync(0xffffffffu, mx0, 1));
        mx0 = fmaxf(mx0, __shfl_xor_sync(0xffffffffu, mx0, 2));
        mx1 = fmaxf(mx1, __shfl_xor_sync(0xffffffffu, mx1, 1));
        mx1 = fmaxf(mx1, __shfl_xor_sync(0xffffffffu, mx1, 2));

        float mn0 = fmaxf(m0, mx0), mn1 = fmaxf(m1, mx1);
        float al0 = __expf(m0 - mn0), al1 = __expf(m1 - mn1);
        float s0 = 0.f, s1 = 0.f;
        #pragma unroll
        for (int ni = 0; ni < 8; ni++) {
            S[ni][0] = __expf(S[ni][0] - mn0);
            S[ni][1] = __expf(S[ni][1] - mn0);
            S[ni][2] = __expf(S[ni][2] - mn1);
            S[ni][3] = __expf(S[ni][3] - mn1);
            s0 += S[ni][0] + S[ni][1];
            s1 += S[ni][2] + S[ni][3];
        }
        s0 += __shfl_xor_sync(0xffffffffu, s0, 1);
        s0 += __shfl_xor_sync(0xffffffffu, s0, 2);
        s1 += __shfl_xor_sync(0xffffffffu, s1, 1);
        s1 += __shfl_xor_sync(0xffffffffu, s1, 2);
        l0 = l0 * al0 + s0;
        l1 = l1 * al1 + s1;
        m0 = mn0; m1 = mn1;

        #pragma unroll
        for (int ni = 0; ni < 16; ni++) {
            O[ni][0] *= al0; O[ni][1] *= al0;
            O[ni][2] *= al1; O[ni][3] *= al1;
        }

        // V(kt) ready
        if (more) { CP_WAIT(1); } else { CP_WAIT(0); }
        __syncthreads();

        // P -> per-warp smem (tf32) to adopt the A-fragment layout
        #pragma unroll
        for (int ni = 0; ni < 8; ni++) {
            Pw[g * 68 + ni * 8 + 2 * tg]           = f2tf32(S[ni][0]);
            Pw[g * 68 + ni * 8 + 2 * tg + 1]       = f2tf32(S[ni][1]);
            Pw[(g + 8) * 68 + ni * 8 + 2 * tg]     = f2tf32(S[ni][2]);
            Pw[(g + 8) * 68 + ni * 8 + 2 * tg + 1] = f2tf32(S[ni][3]);
        }
        __syncwarp();

        // O += P * V
        #pragma unroll
        for (int ks = 0; ks < 8; ks++) {
            uint32_t a0 = Pw[g * 68 + ks * 8 + tg];
            uint32_t a1 = Pw[(g + 8) * 68 + ks * 8 + tg];
            uint32_t a2 = Pw[g * 68 + ks * 8 + 4 + tg];
            uint32_t a3 = Pw[(g + 8) * 68 + ks * 8 + 4 + tg];
            #pragma unroll
            for (int ni = 0; ni < 16; ni++) {
                uint32_t b0 = Vs[(ks * 8 + tg) * 136 + ni * 8 + g];
                uint32_t b1 = Vs[(ks * 8 + 4 + tg) * 136 + ni * 8 + g];
                mma_tf32(O[ni], a0, a1, a2, a3, b0, b1);
            }
        }

        // all warps done reading V(kt) -> stage V(kt+1)
        __syncthreads();
        if (more) {
            const float* vp = vbase + (size_t)((kt + 1) << 6) * QKV_N;
            uint32_t vb = sbase + (uint32_t)(ATT_Q_W + 2 * ATT_K_W) * 4u;
            #pragma unroll
            for (int it = 0; it < 8; it++) {
                int i = tid + it * 256;
                int r = i >> 5, c = (i & 31) << 2;
                cp16(vb + (uint32_t)(r * 136 + c) * 4u, vp + (size_t)r * QKV_N + c);
            }
            CP_COMMIT();
        }
    }

    // normalize and write out, tf32-rounded for the O-proj GEMM
    float il0 = 1.f / l0, il1 = 1.f / l1;
    float* op = out + (size_t)(q0 + wr) * QS + h * HDIM;
    #pragma unroll
    for (int ni = 0; ni < 16; ni++) {
        int c = ni * 8 + 2 * tg;
        *(uint2*)(op + (size_t)g * QS + c) =
            make_uint2(f2tf32(O[ni][0] * il0), f2tf32(O[ni][1] * il0));
        *(uint2*)(op + (size_t)(g + 8) * QS + c) =
            make_uint2(f2tf32(O[ni][2] * il1), f2tf32(O[ni][3] * il1));
    }
}

// ---------------- launcher ----------------
extern "C" void kernel_launch(void* const* d_in, const int* in_sizes, int n_in,
                              void* d_out, int out_size)
{
    const int*   positions = (const int*)d_in[0];
    const float* hidden    = (const float*)d_in[1];
    const float* w_qkv     = (const float*)d_in[2];
    const float* w_o       = (const float*)d_in[3];
    const float* qw        = (const float*)d_in[4];
    const float* kw        = (const float*)d_in[5];
    float*       out       = (float*)d_out;

    float *qkv, *att, *rope, *hid_t, *wqkv_t, *wo_t;
    cudaGetSymbolAddress((void**)&qkv,    g_qkv);
    cudaGetSymbolAddress((void**)&att,    g_att);
    cudaGetSymbolAddress((void**)&rope,   g_rope);
    cudaGetSymbolAddress((void**)&hid_t,  g_hid_t);
    cudaGetSymbolAddress((void**)&wqkv_t, g_wqkv_t);
    cudaGetSymbolAddress((void**)&wo_t,   g_wo_t);

    cudaFuncSetAttribute(attn_kernel,
                         cudaFuncAttributeMaxDynamicSharedMemorySize, ATT_SMEM);
    cudaFuncSetAttribute(gemm_tf32_kernel,
                         cudaFuncAttributeMaxDynamicSharedMemorySize, GEMM_SMEM);

    // pre-round GEMM inputs to tf32
    {
        int n4;
        n4 = (T_TOK * HID) / 4;
        tf32_round_kernel<<<(n4 + 255) / 256, 256>>>(hid_t, hidden, n4);
        n4 = (HID * QKV_N) / 4;
        tf32_round_kernel<<<(n4 + 255) / 256, 256>>>(wqkv_t, w_qkv, n4);
        n4 = (QS * HID) / 4;
        tf32_round_kernel<<<(n4 + 255) / 256, 256>>>(wo_t, w_o, n4);
    }

    build_rope_kernel<<<(T_TOK * 64 + 255) / 256, 256>>>(rope, positions);

    // qkv = hidden @ w_qkv   [4096,2048]x[2048,4096]
    gemm_tf32_kernel<<<dim3(QKV_N / 128, T_TOK / 128), 256, GEMM_SMEM>>>(
        hid_t, wqkv_t, qkv, T_TOK, QKV_N, HID);

    // norm+rope q/k (writes tf32-rounded, q pre-scaled) and round v
    norm_rope_kernel<<<dim3(T_TOK, NHEAD + 2 * NKVH), 128>>>(qkv, qw, kw, rope);

    attn_kernel<<<dim3(T_TOK / 128, NHEAD), 256, ATT_SMEM>>>(qkv, att);

    // out = att @ w_o   [4096,2048]x[2048,2048]
    gemm_tf32_kernel<<<dim3(HID / 128, T_TOK / 128), 256, GEMM_SMEM>>>(
        att, wo_t, out, T_TOK, HID, QS);
}